// round 2
// baseline (speedup 1.0000x reference)
#include <cuda_runtime.h>
#include <stdint.h>

#define Bq   2
#define Cin  4
#define Tt   512
#define Ff   1025
#define Kb   256
#define Dd   128
#define C2o  4
#define WBMAX 64
#define KEMAX (4*WBMAX)

// Scratch (static device globals; no allocation at runtime)
__device__ float g_xT[Bq*Tt*Ff*Cin];          // x transposed to [b,t,f,c]
__device__ float g_outT[Bq*Tt*Ff*C2o];        // accumulation buffer [b,t,f,c2]
__device__ float g_Weff[(size_t)Kb*KEMAX*KEMAX]; // per-band fused W1@W2 (scaled)
__device__ float g_beff[Kb*KEMAX];            // per-band fused bias
__device__ int   g_nnz[Kb];

// ---------------------------------------------------------------------------
// Kernel 1: transpose x (B,C,T,F) -> xT (B,T,F,C) so band gathers are
// contiguous float4 runs.
// ---------------------------------------------------------------------------
__global__ __launch_bounds__(256) void k_transpose_x(const float* __restrict__ x)
{
    int p = blockIdx.x * 256 + threadIdx.x;          // p over (b,t,f)
    if (p >= Bq*Tt*Ff) return;
    int f  = p % Ff;
    int bt = p / Ff;
    int t  = bt % Tt;
    int b  = bt / Tt;
    float4 v;
    v.x = x[(((size_t)(b*Cin+0)*Tt + t)*Ff) + f];
    v.y = x[(((size_t)(b*Cin+1)*Tt + t)*Ff) + f];
    v.z = x[(((size_t)(b*Cin+2)*Tt + t)*Ff) + f];
    v.w = x[(((size_t)(b*Cin+3)*Tt + t)*Ff) + f];
    reinterpret_cast<float4*>(g_xT)[p] = v;
}

// ---------------------------------------------------------------------------
// Kernel 2: per-band fused weights.
//   W_eff[k][i][o] = mel[k][w_i] * (sum_d W1[k][i][d]*W2[k][d][o]) / ola[f(w_o)]
//   b_eff[k][o]    = (b1[k] . W2[k][:,o] + b2[k][o]) / ola[f(w_o)]
// Only the nnz-bounded (4*nnz)^2 block is computed. grid = (Kb, i-tiles of 32).
// ---------------------------------------------------------------------------
__global__ __launch_bounds__(256) void k_weff(
    const float* __restrict__ W1, const float* __restrict__ b1,
    const float* __restrict__ W2, const float* __restrict__ b2,
    const int*   __restrict__ nzidx, const float* __restrict__ nzmel,
    const float* __restrict__ mask,  const float* __restrict__ ola, int Wb)
{
    extern __shared__ __align__(16) float sm[];
    const int k   = blockIdx.x;
    const int KeW = 4*Wb;
    const int iBase = blockIdx.y * 32;

    float* W1s = sm;                 // [32][128]   (rows iBase..)
    float* W2s = sm + 32*128;        // [128][Ke4]  compact
    float* rs  = W2s + 128*KeW;      // row scale (mel), size KeW
    float* cs  = rs + KeW;           // col scale (1/ola), size KeW

    __shared__ int s_nnz;
    if (threadIdx.x == 0) {
        int n = 0;
        for (int w = 0; w < Wb; ++w) n += (mask[k*Wb + w] > 0.5f);
        s_nnz = n;
        if (blockIdx.y == 0) g_nnz[k] = n;
    }
    __syncthreads();
    const int nnz = s_nnz;
    const int Ke4 = 4*nnz;                      // always a multiple of 4
    if (iBase >= Ke4) return;
    const int ni = min(32, Ke4 - iBase);        // multiple of 4

    // stage W1 rows (contiguous) and the used W2 columns
    for (int j = threadIdx.x; j < ni*Dd; j += 256)
        W1s[j] = W1[((size_t)k*KeW + iBase)*Dd + j];
    for (int j = threadIdx.x; j < Dd*Ke4; j += 256) {
        int d = j / Ke4, o = j - d*Ke4;
        W2s[j] = W2[((size_t)k*Dd + d)*KeW + o];
    }
    for (int w = threadIdx.x; w < nnz; w += 256) {
        float m   = nzmel[k*Wb + w];
        float inv = 1.0f / ola[nzidx[k*Wb + w]];
        rs[4*w+0]=m;   rs[4*w+1]=m;   rs[4*w+2]=m;   rs[4*w+3]=m;
        cs[4*w+0]=inv; cs[4*w+1]=inv; cs[4*w+2]=inv; cs[4*w+3]=inv;
    }
    __syncthreads();

    const int nrt = ni >> 2, nct = Ke4 >> 2;
    for (int tile = threadIdx.x; tile < nrt*nct; tile += 256) {
        int tr = tile / nct, tc = tile - tr*nct;
        float acc[4][4] = {};
        const float* a = &W1s[(tr*4)*Dd];
        const float* bp = &W2s[tc*4];
        for (int d = 0; d < Dd; ++d) {
            float a0 = a[d], a1 = a[Dd+d], a2 = a[2*Dd+d], a3 = a[3*Dd+d];
            float4 bv = *reinterpret_cast<const float4*>(bp); bp += Ke4;
            acc[0][0]+=a0*bv.x; acc[0][1]+=a0*bv.y; acc[0][2]+=a0*bv.z; acc[0][3]+=a0*bv.w;
            acc[1][0]+=a1*bv.x; acc[1][1]+=a1*bv.y; acc[1][2]+=a1*bv.z; acc[1][3]+=a1*bv.w;
            acc[2][0]+=a2*bv.x; acc[2][1]+=a2*bv.y; acc[2][2]+=a2*bv.z; acc[2][3]+=a2*bv.w;
            acc[3][0]+=a3*bv.x; acc[3][1]+=a3*bv.y; acc[3][2]+=a3*bv.z; acc[3][3]+=a3*bv.w;
        }
        int gi = iBase + tr*4, go = tc*4;
        #pragma unroll
        for (int rr = 0; rr < 4; ++rr) {
            float rsc = rs[gi+rr];
            #pragma unroll
            for (int oo = 0; oo < 4; ++oo)
                g_Weff[((size_t)k*KeW + gi+rr)*KeW + go+oo] = rsc*cs[go+oo]*acc[rr][oo];
        }
    }

    if (blockIdx.y == 0) {
        for (int o = threadIdx.x; o < Ke4; o += 256) {
            float s = b2[(size_t)k*KeW + o];
            for (int d = 0; d < Dd; ++d) s += b1[k*Dd + d] * W2s[d*Ke4 + o];
            g_beff[k*KEMAX + o] = s * cs[o];
        }
    }
}

// ---------------------------------------------------------------------------
// Kernel 3: main per-band GEMM + scatter.
//   For band k, rows r in [r0,r0+128): y[r][o] = sum_ke A[r][ke]*Weff[ke][o]+beff[o]
//   atomicAdd into outT[r][f(w_o)][c2].
// Per-block column count dispatched to compile-time CC for register tiling.
// ---------------------------------------------------------------------------
template <int CC>
__device__ __forceinline__ void main_compute(
    const float* __restrict__ As, const float* __restrict__ Ws,
    const float* __restrict__ bsm, const int* __restrict__ sidx,
    int Ke4, int r0)
{
    const int NE = CC*16;
    const int tid = threadIdx.x, tx = tid & 15, ty = tid >> 4;
    float acc[8][CC];
    #pragma unroll
    for (int rr = 0; rr < 8; ++rr)
        #pragma unroll
        for (int cc = 0; cc < CC; ++cc) acc[rr][cc] = 0.0f;

    for (int ke = 0; ke < Ke4; ++ke) {
        float wr[CC];
        #pragma unroll
        for (int cc = 0; cc < CC; ++cc) wr[cc] = Ws[ke*NE + cc*16 + tx];
        #pragma unroll
        for (int rr = 0; rr < 8; ++rr) {
            float a = As[(ty*8+rr)*Ke4 + ke];
            #pragma unroll
            for (int cc = 0; cc < CC; ++cc) acc[rr][cc] += a * wr[cc];
        }
    }

    #pragma unroll
    for (int rr = 0; rr < 8; ++rr) {
        size_t rbase = (size_t)(r0 + ty*8 + rr) * Ff * C2o;
        #pragma unroll
        for (int cc = 0; cc < CC; ++cc) {
            int o = cc*16 + tx;
            if (o < Ke4) {
                int f = sidx[o >> 2];
                atomicAdd(&g_outT[rbase + (size_t)f*C2o + (o & 3)],
                          acc[rr][cc] + bsm[o]);
            }
        }
    }
}

__device__ void main_compute_gen(
    const float* As, const float* Ws, const float* bsm,
    const int* sidx, int Ke4, int NE, int r0)
{
    for (int p = threadIdx.x; p < 128*Ke4; p += 256) {
        int lr = p / Ke4, o = p - lr*Ke4;
        float s = bsm[o];
        for (int ke = 0; ke < Ke4; ++ke) s += As[lr*Ke4+ke] * Ws[ke*NE+o];
        int f = sidx[o >> 2];
        atomicAdd(&g_outT[((size_t)(r0+lr)*Ff + f)*C2o + (o & 3)], s);
    }
}

__global__ __launch_bounds__(256, 1) void k_main(const int* __restrict__ nzidx, int Wb)
{
    extern __shared__ __align__(16) float sm[];
    __shared__ int sidx[WBMAX];
    const int k    = blockIdx.x;
    const int nnz  = g_nnz[k];
    const int Ke4  = 4*nnz;
    const int CCk  = (Ke4 + 15) >> 4;
    const int NE   = CCk * 16;
    const int KeW  = 4*Wb;
    const int r0   = blockIdx.y * 128;
    const int tid  = threadIdx.x;

    if (tid < nnz) sidx[tid] = nzidx[k*Wb + tid];

    float* As  = sm;                    // [128][Ke4]
    float* Ws  = sm + 128*Ke4;          // [Ke4][NE] (cols zero-padded)
    float* bsm = Ws + Ke4*NE;           // [NE]

    for (int j = tid; j < Ke4*NE; j += 256) {
        int i = j / NE, o = j - i*NE;
        Ws[j] = (o < Ke4) ? g_Weff[((size_t)k*KeW + i)*KeW + o] : 0.0f;
    }
    for (int o = tid; o < NE; o += 256)
        bsm[o] = (o < Ke4) ? g_beff[k*KEMAX + o] : 0.0f;
    __syncthreads();

    // gather A: contiguous float4 per (row, bin)
    for (int p = tid; p < 128*nnz; p += 256) {
        int lr = p / nnz, w = p - lr*nnz;
        int f = sidx[w];
        float4 v = *reinterpret_cast<const float4*>(
            &g_xT[((size_t)(r0 + lr)*Ff + f) * Cin]);
        *reinterpret_cast<float4*>(&As[lr*Ke4 + 4*w]) = v;
    }
    __syncthreads();

    switch (CCk) {
        case 1:  main_compute<1 >(As, Ws, bsm, sidx, Ke4, r0); break;
        case 2:  main_compute<2 >(As, Ws, bsm, sidx, Ke4, r0); break;
        case 3:  main_compute<3 >(As, Ws, bsm, sidx, Ke4, r0); break;
        case 4:  main_compute<4 >(As, Ws, bsm, sidx, Ke4, r0); break;
        case 5:  main_compute<5 >(As, Ws, bsm, sidx, Ke4, r0); break;
        case 6:  main_compute<6 >(As, Ws, bsm, sidx, Ke4, r0); break;
        case 7:  main_compute<7 >(As, Ws, bsm, sidx, Ke4, r0); break;
        case 8:  main_compute<8 >(As, Ws, bsm, sidx, Ke4, r0); break;
        case 9:  main_compute<9 >(As, Ws, bsm, sidx, Ke4, r0); break;
        case 10: main_compute<10>(As, Ws, bsm, sidx, Ke4, r0); break;
        case 11: main_compute<11>(As, Ws, bsm, sidx, Ke4, r0); break;
        default: main_compute_gen(As, Ws, bsm, sidx, Ke4, NE, r0); break;
    }
}

// ---------------------------------------------------------------------------
// Kernel 4: transpose outT (B,T,F,C2) -> out (B,C2,T,F)
// ---------------------------------------------------------------------------
__global__ __launch_bounds__(256) void k_out(float* __restrict__ out)
{
    int p = blockIdx.x * 256 + threadIdx.x;
    if (p >= Bq*C2o*Tt*Ff) return;
    int f  = p % Ff;
    int q  = p / Ff;
    int t  = q % Tt;
    int q2 = q / Tt;
    int c2 = q2 % C2o;
    int b  = q2 / C2o;
    out[p] = g_outT[(((size_t)(b*Tt + t)*Ff) + f)*C2o + c2];
}

// ---------------------------------------------------------------------------
extern "C" void kernel_launch(void* const* d_in, const int* in_sizes, int n_in,
                              void* d_out, int out_size)
{
    const float* x     = (const float*)d_in[0];
    const float* W1    = (const float*)d_in[1];
    const float* b1    = (const float*)d_in[2];
    const float* W2    = (const float*)d_in[3];
    const float* b2    = (const float*)d_in[4];
    const int*   nzidx = (const int*)  d_in[5];
    const float* nzmel = (const float*)d_in[6];
    const float* mask  = (const float*)d_in[7];
    const float* ola   = (const float*)d_in[8];

    const int Wb    = in_sizes[5] / Kb;
    const int KeW   = 4*Wb;
    const int NEmax = ((KeW + 15)/16)*16;

    void* outT_ptr = nullptr;
    cudaGetSymbolAddress(&outT_ptr, g_outT);
    cudaMemsetAsync(outT_ptr, 0, sizeof(float)*(size_t)Bq*Tt*Ff*C2o, 0);

    k_transpose_x<<<(Bq*Tt*Ff + 255)/256, 256>>>(x);

    int weff_smem = (32*Dd + Dd*KeW + 2*KeW) * (int)sizeof(float);
    cudaFuncSetAttribute(k_weff, cudaFuncAttributeMaxDynamicSharedMemorySize, weff_smem);
    dim3 gw(Kb, (KeW + 31)/32);
    k_weff<<<gw, 256, weff_smem>>>(W1, b1, W2, b2, nzidx, nzmel, mask, ola, Wb);

    int main_smem = (128*KeW + KeW*NEmax + NEmax) * (int)sizeof(float);
    cudaFuncSetAttribute(k_main, cudaFuncAttributeMaxDynamicSharedMemorySize, main_smem);
    k_main<<<dim3(Kb, 8), 256, main_smem>>>(nzidx, Wb);

    k_out<<<(Bq*C2o*Tt*Ff + 255)/256, 256>>>((float*)d_out);
}